// round 10
// baseline (speedup 1.0000x reference)
#include <cuda_runtime.h>

#define NGRID 10000
#define NSTEP 365
#define NMUL 16
#define NEARZERO 1e-5f
#define TBATCH 5            // 365 = 5 * 73
#define NBATCH (NSTEP / TBATCH)
#define XSTRIDE (NGRID * 3)
#define RSTRIDE 36          // smem row stride (floats): 32 data + 4 pad

__global__ __launch_bounds__(32)
void hbv_waterloss_kernel(
    const float* __restrict__ x,     // (365, 10000, 3) P,T,PET
    const float* __restrict__ praw,  // (365, 10000, 3, 16) -- only step 364 used
    const float* __restrict__ wraw,  // (10000, 13, 16)
    const float* __restrict__ ac,    // (10000,)
    float* __restrict__ out)         // (365, 10000)
{
    __shared__ float  red[2][TBATCH * RSTRIDE];
    __shared__ float4 fbuf[2][TBATCH * 2];   // {P,T,E,pad} per (step, grid-half)

    const int lane = threadIdx.x;                  // 0..31
    const int g0   = blockIdx.x * 2;               // warp's grid pair base
    const int g = g0 + (lane >> 4);                // this thread's grid cell
    const int m = lane & 15;                       // multiplier index
    const int ch = lane >> 4;                      // compute half (0/1)

    // ---- forcing-loader role: lanes 0..29 fetch one float of a batch ----
    const bool fload = lane < 30;
    const int  fs = lane / 3;                      // slot 0..9  (= k*2 + h)
    const int  fc = lane - fs * 3;                 // component 0..2 (P/T/E)
    const int  fk = fs >> 1;                       // step within batch
    const int  fh = fs & 1;                        // grid half
    const float* fp = x + (size_t)fk * XSTRIDE + (size_t)(g0 + fh) * 3 + fc;

    // ---- parameter scaling (HBV params from last timestep: static_idx = -1) ----
    const float* pr = praw + ((size_t)364 * NGRID + g) * (3 * NMUL) + m;
    const float parBETA   = 1.0f  + pr[0]      * 5.0f;
    const float parK0     = 0.05f + pr[16]     * 0.85f;
    const float parBETAET = 0.3f  + pr[32]     * 4.7f;

    const float* wr = wraw + (size_t)g * (13 * NMUL) + m;
    const float parFC    = 50.0f  + wr[0]   * 950.0f;
    const float parK1    = 0.01f  + wr[16]  * 0.49f;
    const float parK2    = 0.001f + wr[32]  * 0.199f;
    const float parLP    = 0.2f   + wr[48]  * 0.8f;
    const float parPERC  =          wr[64]  * 10.0f;
    const float parUZL   =          wr[80]  * 100.0f;
    const float parTT    = -2.5f  + wr[96]  * 5.0f;
    const float parCFMAX = 0.5f   + wr[112] * 9.5f;
    const float parCFR   =          wr[128] * 0.1f;
    const float parCWH   =          wr[144] * 0.2f;
    const float parC     =          wr[160];
    const float parTR    =          wr[176] * 20.0f;
    const float parAc    =          wr[192] * 2500.0f;

    // ---- regional flow (time-invariant per (g,m)) ----
    const float acm = ac[g];
    float regional_flow;
    {
        const float rf = fminf(fmaxf((acm - parAc) * 0.001f, -1.0f), 1.0f);
        if (acm < 2500.0f) {
            regional_flow = rf * parTR;
        } else {
            const float e = fminf(fmaxf(-(acm - 2500.0f) * (1.0f / 50.0f), -10.0f), 0.0f);
            regional_flow = expf(e) * parTR;
        }
    }

    const float invFC       = 1.0f / parFC;
    const float invLPFC     = 1.0f / (parLP * parFC);
    const float negCFRCFMAX = -(parCFR * parCFMAX);
    const float oneMK1      = 1.0f - parK1;
    const float oneMK2      = 1.0f - parK2;

    float SNOWPACK = 0.001f, MELTWATER = 0.001f, SM = 0.001f, SUZ = 0.001f, SLZ = 0.001f;

    // reduction job: lanes 0..9 -> (step jk, half jh)
    const int  jk = lane >> 1;
    const int  jh = lane & 1;
    const bool jactive = (lane < 10);
    float* const outg = out + g0;

    // ---- prologue: stage batch 0 ----
    if (fload) {
        const float v = __ldg(fp);
        reinterpret_cast<float*>(fbuf[0])[fs * 4 + fc] = v;
    }
    __syncthreads();

    #pragma unroll 1
    for (int tb = 0; tb < NBATCH; ++tb) {
        // ---- issue next batch's forcing load (1 LDG warp-wide) ----
        float nf = 0.0f;
        const bool more = (tb + 1 < NBATCH);
        if (fload && more)
            nf = __ldg(fp + (size_t)(tb + 1) * (TBATCH * XSTRIDE));

        const int buf = tb & 1;

        // ---- compute TBATCH steps from staged forcing ----
        #pragma unroll
        for (int k = 0; k < TBATCH; ++k) {
            const float4 f = fbuf[buf][k * 2 + ch];
            const float Pm = f.x, Tm = f.y, PETm = f.z;

            // ---- snow routine ----
            const float dtt  = Tm - parTT;
            const float RAIN = (dtt >= 0.0f) ? Pm : 0.0f;
            SNOWPACK += Pm - RAIN;
            const float melt = fminf(fmaxf(parCFMAX * dtt, 0.0f), SNOWPACK);
            MELTWATER += melt;
            SNOWPACK  -= melt;
            const float refreezing = fminf(fmaxf(negCFRCFMAX * dtt, 0.0f), MELTWATER);
            SNOWPACK  += refreezing;
            MELTWATER -= refreezing;
            const float tosoil = fmaxf(MELTWATER - parCWH * SNOWPACK, 0.0f);
            MELTWATER -= tosoil;

            // ---- soil routine ----
            const float soil_wetness = fminf(__powf(SM * invFC, parBETA), 1.0f);
            const float rt = RAIN + tosoil;
            const float recharge = rt * soil_wetness;
            SM += rt - recharge;
            const float excess = fmaxf(SM - parFC, 0.0f);
            SM -= excess;
            const float evapfactor = fminf(__powf(SM * invLPFC, parBETAET), 1.0f);
            SM = fmaxf(SM - PETm * evapfactor, NEARZERO);
            const float capillary = (parC * SLZ) * (1.0f - fminf(SM * invFC, 1.0f));
            SM  = fmaxf(SM + capillary, NEARZERO);
            SLZ = fmaxf(SLZ - capillary, NEARZERO);

            // ---- response routine ----
            SUZ += recharge + excess;
            const float PERC = fminf(SUZ, parPERC);
            SUZ -= PERC;
            const float Q0 = parK0 * fmaxf(SUZ - parUZL, 0.0f);
            SUZ -= Q0;
            const float Q1 = parK1 * SUZ;
            SUZ *= oneMK1;
            SLZ = fmaxf(SLZ + PERC + regional_flow, 0.0f);
            const float Q2 = parK2 * SLZ;
            SLZ *= oneMK2;

            red[buf][k * RSTRIDE + lane] = Q0 + Q1 + Q2;
        }

        // ---- stage next batch's forcing (LDG latency now covered) ----
        if (fload && more)
            reinterpret_cast<float*>(fbuf[buf ^ 1])[fs * 4 + fc] = nf;

        __syncthreads();   // orders red writes AND fbuf staging (single warp: ~3 cyc)

        // ---- lanes 0..9: sum one (step, grid-half) row of 16 ----
        if (jactive) {
            const float4* p = reinterpret_cast<const float4*>(
                &red[buf][jk * RSTRIDE + jh * 16]);
            const float4 a = p[0], b = p[1], c = p[2], d = p[3];
            const float4 s0 = make_float4(a.x + b.x, a.y + b.y, a.z + b.z, a.w + b.w);
            const float4 s1 = make_float4(c.x + d.x, c.y + d.y, c.z + d.z, c.w + d.w);
            const float sum = ((s0.x + s1.x) + (s0.y + s1.y))
                            + ((s0.z + s1.z) + (s0.w + s1.w));
            outg[((size_t)tb * TBATCH + jk) * NGRID + jh] = sum * (1.0f / 16.0f);
        }
    }
}

extern "C" void kernel_launch(void* const* d_in, const int* in_sizes, int n_in,
                              void* d_out, int out_size) {
    const float* x  = nullptr;
    const float* pr = nullptr;
    const float* wr = nullptr;
    const float* ac = nullptr;
    for (int i = 0; i < n_in; ++i) {
        const long n = (long)in_sizes[i];
        if      (n == 365L * NGRID * 3)            x  = (const float*)d_in[i];
        else if (n == 365L * NGRID * 3 * NMUL)     pr = (const float*)d_in[i];
        else if (n == (long)NGRID * 13 * NMUL)     wr = (const float*)d_in[i];
        else if (n == (long)NGRID)                 ac = (const float*)d_in[i];
    }
    // measured-best geometry: one warp per block, 5000 blocks (covers all 160000 chains)
    hbv_waterloss_kernel<<<5000, 32>>>(x, pr, wr, ac, (float*)d_out);
}